// round 6
// baseline (speedup 1.0000x reference)
#include <cuda_runtime.h>
#include <math.h>

// Problem constants
#define N_CAPS 64
#define CAPS_DIM 16
#define OUT_DIM 128
#define P_DIM 1152
#define BATCH 256
#define BO (BATCH * OUT_DIM)       // 32768
#define PSPLIT 24
#define PCHUNK (P_DIM / PSPLIT)    // 48
#define WROW 132                   // padded row stride (float4-aligned, conflict-free)

// Scratch (no cudaMalloc allowed)
__device__ __align__(16) float g_partial[PSPLIT * BO];      // 3 MB
__device__ __align__(16) float g_wsum [N_CAPS * OUT_DIM];   // [n][o]
__device__ __align__(16) float g_wsumT[OUT_DIM * N_CAPS];   // [o][n]

// ---------------------------------------------------------------------------
// Kernel 1 (fused): grid (32, PSPLIT+1) x 256.
//  y < PSPLIT : X partials. x is (P, B, O) => matrix (P, 32768 floats).
//  y == PSPLIT: Wsum[n,o] = sum_c w[n,c,o], both layouts, hidden in the
//               HBM-bound reduction.
// ---------------------------------------------------------------------------
__global__ void __launch_bounds__(256) reduce_x_kernel(const float4* __restrict__ x4,
                                                       const float4* __restrict__ w4) {
    int chunk = blockIdx.y;

    if (chunk == PSPLIT) {
        int i = blockIdx.x * blockDim.x + threadIdx.x;   // float4 index into Wsum
        if (i >= N_CAPS * (OUT_DIM / 4)) return;
        int n  = i >> 5;                                 // 32 float4 per row
        int o4 = i & 31;
        const float4* base = w4 + (size_t)n * (CAPS_DIM * OUT_DIM / 4) + o4;
        float4 acc = make_float4(0.f, 0.f, 0.f, 0.f);
#pragma unroll
        for (int c = 0; c < CAPS_DIM; ++c) {
            float4 v = __ldg(&base[c * (OUT_DIM / 4)]);
            acc.x += v.x; acc.y += v.y; acc.z += v.z; acc.w += v.w;
        }
        reinterpret_cast<float4*>(g_wsum)[i] = acc;
        int o = o4 * 4;
        g_wsumT[(o + 0) * N_CAPS + n] = acc.x;
        g_wsumT[(o + 1) * N_CAPS + n] = acc.y;
        g_wsumT[(o + 2) * N_CAPS + n] = acc.z;
        g_wsumT[(o + 3) * N_CAPS + n] = acc.w;
        return;
    }

    int col = blockIdx.x * blockDim.x + threadIdx.x;     // 0..8191 (float4 units)
    const float4* base = x4 + (size_t)(chunk * PCHUNK) * (BO / 4) + col;

    float4 acc = make_float4(0.f, 0.f, 0.f, 0.f);
#pragma unroll 8
    for (int p = 0; p < PCHUNK; ++p) {
        float4 v = __ldcs(&base[(size_t)p * (BO / 4)]);
        acc.x += v.x; acc.y += v.y; acc.z += v.z; acc.w += v.w;
    }
    reinterpret_cast<float4*>(g_partial)[chunk * (BO / 4) + col] = acc;
}

// ---------------------------------------------------------------------------
// Kernel 2: routing. One block per batch element, 128 threads (thread t = o).
//  - wreg[n] = Wsum[n][t] in registers (from g_wsumT)  -> s-compute is FFMA-only
//  - sh_w rows (stride 132) for the logits matvec, float4 LDS, all 128 threads
//  - warp 0 owns logits/softmax (2 caps per lane, in-warp shuffles only)
// ---------------------------------------------------------------------------
__global__ void __launch_bounds__(128) routing_kernel(float* __restrict__ out) {
    const int b = blockIdx.x;
    const int t = threadIdx.x;
    const int lane = t & 31;
    const int wid  = t >> 5;
    const int n_id = t & 63;     // cap handled in logits phase
    const int half = t >> 6;     // o-half handled in logits phase

    __shared__ float sh_w[N_CAPS * WROW];   // padded Wsum rows (33.8 KB)
    __shared__ float shrp[OUT_DIM];         // rp vector
    __shared__ float shpart[128];           // logits partials [half][n]
    __shared__ float shc[N_CAPS];           // coeffs
    __shared__ float shred[4];

    // Load Wsum rows into padded shared (16 float4 per thread)
    {
        const float4* w4 = reinterpret_cast<const float4*>(g_wsum);
#pragma unroll
        for (int k = 0; k < (N_CAPS * OUT_DIM / 4) / 128; ++k) {
            int i4 = t + k * 128;
            float4 v = __ldg(&w4[i4]);
            int n = i4 >> 5;
            int o = (i4 & 31) * 4;
            *reinterpret_cast<float4*>(&sh_w[n * WROW + o]) = v;
        }
    }

    // wreg[n] = Wsum[n][t] from transposed layout (16 float4 LDG, L2-hot)
    float wreg[N_CAPS];
    {
        const float4* wt4 = reinterpret_cast<const float4*>(g_wsumT) + t * (N_CAPS / 4);
#pragma unroll
        for (int i = 0; i < N_CAPS / 4; ++i) {
            float4 v = __ldg(&wt4[i]);
            wreg[4 * i + 0] = v.x; wreg[4 * i + 1] = v.y;
            wreg[4 * i + 2] = v.z; wreg[4 * i + 3] = v.w;
        }
    }

    // Finalize X[b, t] from the PSPLIT partials (independent; overlaps above)
    float X = 0.f;
#pragma unroll
    for (int ch = 0; ch < PSPLIT; ++ch)
        X += g_partial[ch * BO + b * OUT_DIM + t];

    if (t < N_CAPS) shc[t] = 1.0f / N_CAPS;
    float logit_a = 0.f, logit_b = 0.f;     // warp 0: caps lane, lane+32
    __syncthreads();

    // ITERATIONS = 3 -> 2 routing updates, then final squash
    for (int iter = 0; iter < 3; ++iter) {
        // s_o = X * sum_n c_n * W[n,o]   (pure FFMA from registers)
        float s = 0.f;
#pragma unroll
        for (int n = 0; n < N_CAPS; ++n)
            s += shc[n] * wreg[n];
        s *= X;

        // block reduce ||s||^2
        float sq = s * s;
#pragma unroll
        for (int off = 16; off > 0; off >>= 1)
            sq += __shfl_xor_sync(0xffffffffu, sq, off);
        if (lane == 0) shred[wid] = sq;
        __syncthreads();
        float tot   = shred[0] + shred[1] + shred[2] + shred[3];
        float scale = sqrtf(tot) / (1.0f + tot);   // norm / (1 + norm^2)

        if (iter == 2) {
            out[b * OUT_DIM + t] = scale * s;      // final squash(coeffs @ xp)
            return;
        }

        // rp to shared
        shrp[t] = scale * s * X;
        __syncthreads();

        // logits partial: thread t -> cap n_id, o-range [half*64, half*64+64)
        {
            const float4* wrow = reinterpret_cast<const float4*>(&sh_w[n_id * WROW]) + half * 16;
            const float4* rp4  = reinterpret_cast<const float4*>(shrp) + half * 16;
            float acc = 0.f;
#pragma unroll
            for (int j = 0; j < 16; ++j) {
                float4 wv = wrow[j];
                float4 rv = rp4[j];
                acc += wv.x * rv.x + wv.y * rv.y + wv.z * rv.z + wv.w * rv.w;
            }
            shpart[t] = acc;    // [half*64 + n]
        }
        __syncthreads();

        // warp 0: accumulate logits (2 caps/lane) + softmax fully in-warp
        if (wid == 0) {
            logit_a += shpart[lane]      + shpart[lane + 64];
            logit_b += shpart[lane + 32] + shpart[lane + 96];
            float m = fmaxf(logit_a, logit_b);
#pragma unroll
            for (int off = 16; off > 0; off >>= 1)
                m = fmaxf(m, __shfl_xor_sync(0xffffffffu, m, off));
            float ea = __expf(logit_a - m);
            float eb = __expf(logit_b - m);
            float sm = ea + eb;
#pragma unroll
            for (int off = 16; off > 0; off >>= 1)
                sm += __shfl_xor_sync(0xffffffffu, sm, off);
            float inv = 1.0f / sm;
            shc[lane]      = ea * inv;
            shc[lane + 32] = eb * inv;
        }
        __syncthreads();
    }
}

// ---------------------------------------------------------------------------
extern "C" void kernel_launch(void* const* d_in, const int* in_sizes, int n_in,
                              void* d_out, int out_size) {
    const float* x = (const float*)d_in[0];             // (1152, 256, 128)
    const float* w = (const float*)d_in[1];             // (64, 16, 128)
    float* out = (float*)d_out;                         // (256, 1, 128)

    dim3 g1(32, PSPLIT + 1);
    reduce_x_kernel<<<g1, 256>>>(reinterpret_cast<const float4*>(x),
                                 reinterpret_cast<const float4*>(w));
    routing_kernel<<<BATCH, 128>>>(out);
}